// round 3
// baseline (speedup 1.0000x reference)
#include <cuda_runtime.h>
#include <cuda_bf16.h>

#define NX    512
#define NPTS  32768
#define CCH   64
#define NB    4
#define PLANE (NX * NX)
#define TILE  32
#define TPB   16              // tiles per batch per axis (512/32)
#define NBINS (NB * TPB * TPB)   // 1024
#define NPTS_TOT (NB * NPTS)     // 131072
#define TH    34              // tile + halo
#define CG    16              // channels per group
#define CST   18              // smem channel stride (floats), even for float2

__device__ int    g_cnt[NBINS];
__device__ int    g_cur[NBINS];
__device__ int    g_off[NBINS];
__device__ float4 g_pts[(size_t)NPTS_TOT * 3];        // 6.3 MB records
__device__ float  g_outT[(size_t)NB * NPTS * CCH];    // (b, n, c) scratch 33.5 MB

// ---------------------------------------------------------------------------
__device__ __forceinline__ void point_pos(const float* coords, int b, int n,
                                          float& posx, float& posy,
                                          int& irx, int& iry) {
    const float cy = coords[((size_t)b * NPTS + n) * 2 + 0];
    const float cx = coords[((size_t)b * NPTS + n) * 2 + 1];
    posx = cx * 511.0f;
    posy = cy * 511.0f;
    irx = (int)rintf(posx);      // jnp.round = half-to-even
    iry = (int)rintf(posy);
}

__global__ void zero_kernel() {
    const int i = blockIdx.x * blockDim.x + threadIdx.x;
    if (i < NBINS) { g_cnt[i] = 0; g_cur[i] = 0; }
}

__global__ __launch_bounds__(256) void count_kernel(const float* __restrict__ coords) {
    const int gid = blockIdx.x * blockDim.x + threadIdx.x;
    if (gid >= NPTS_TOT) return;
    const int b = gid >> 15, n = gid & (NPTS - 1);
    float posx, posy; int irx, iry;
    point_pos(coords, b, n, posx, posy, irx, iry);
    const int bin = b * (TPB * TPB) + (irx >> 5) * TPB + (iry >> 5);
    atomicAdd(&g_cnt[bin], 1);
}

__global__ __launch_bounds__(1024) void scan_kernel() {
    __shared__ int s[NBINS];
    const int t = threadIdx.x;
    int v = g_cnt[t];
    s[t] = v;
    __syncthreads();
    #pragma unroll
    for (int d = 1; d < NBINS; d <<= 1) {
        int u = (t >= d) ? s[t - d] : 0;
        __syncthreads();
        s[t] += u;
        __syncthreads();
    }
    g_off[t] = s[t] - v;   // exclusive prefix
}

__global__ __launch_bounds__(256) void scatter_kernel(const float* __restrict__ coords) {
    const int gid = blockIdx.x * blockDim.x + threadIdx.x;
    if (gid >= NPTS_TOT) return;
    const int b = gid >> 15, n = gid & (NPTS - 1);
    float posx, posy; int irx, iry;
    point_pos(coords, b, n, posx, posy, irx, iry);
    const float rx = (float)irx, ry = (float)iry;

    float wx[3] = {0.f, 0.f, 0.f};
    float wy[3] = {0.f, 0.f, 0.f};
    #pragma unroll
    for (int j = 0; j < 9; j++) {
        const float o  = 1.5f - 0.375f * (float)j;           // off_n[j]
        const float px = fminf(fmaxf(rx - o, 0.f), 512.f);   // clip hi = nx (ref quirk)
        const float py = fminf(fmaxf(ry - o, 0.f), 512.f);
        const float dx = px - posx;
        const float dy = py - posy;
        wx[j / 3] += __expf(-2.f * dx * dx);   // normal const cancels in normalization
        wy[j / 3] += __expf(-2.f * dy * dy);
    }
    float w9[9]; float ssum = 0.f;
    #pragma unroll
    for (int a = 0; a < 3; a++)
        #pragma unroll
        for (int c2 = 0; c2 < 3; c2++) { const float w = wx[a] * wy[c2]; w9[a*3+c2] = w; ssum += w; }
    const float inv = 1.0f / ssum;
    #pragma unroll
    for (int k = 0; k < 9; k++) w9[k] *= inv;

    const int bin  = b * (TPB * TPB) + (irx >> 5) * TPB + (iry >> 5);
    const int slot = atomicAdd(&g_cur[bin], 1);
    const size_t p = (size_t)(g_off[bin] + slot) * 3;
    g_pts[p + 0] = make_float4(w9[0], w9[1], w9[2], w9[3]);
    g_pts[p + 1] = make_float4(w9[4], w9[5], w9[6], w9[7]);
    g_pts[p + 2] = make_float4(w9[8], __int_as_float(n), __int_as_float(irx), __int_as_float(iry));
}

// ---------------------------------------------------------------------------
// Main: block = (bin, channel-group). Loads 34x34 x 16ch haloed tile from NCHW
// into smem, then points of the bin: 9 taps x 16 channels each.
// Lane mapping: cp = lane&7 (channel pair), q = lane>>3 (point in group of 4).
// ---------------------------------------------------------------------------
__global__ __launch_bounds__(256) void main_kernel(const float* __restrict__ x) {
    extern __shared__ float s[];   // [TH*TH][CST], CST=18, 83232 B

    const int blk = blockIdx.x;
    const int cg  = blk & 3;              // channel group
    const int bin = blk >> 2;
    const int b   = bin >> 8;
    const int tl  = bin & 255;
    const int tX  = tl >> 4;              // tile index along dim -2 (ix)
    const int tY  = tl & 15;              // along contiguous dim -1 (iy)
    const int oX  = tX * TILE, oY = tY * TILE;
    const int c0  = cg * CG;

    const int tid = threadIdx.x;

    // ---- load tile+halo for 16 channels ----
    const float* xb = x + ((size_t)b * CCH + c0) * PLANE;
    for (int i = tid; i < CG * TH * TH; i += 256) {
        const int c  = i / (TH * TH);
        const int r  = i - c * (TH * TH);
        const int lx = r / TH;
        const int ly = r - lx * TH;
        const int gx = min(max(oX - 1 + lx, 0), NX - 1);
        const int gy = min(max(oY - 1 + ly, 0), NX - 1);
        s[(size_t)r * CST + c] = __ldg(xb + (size_t)c * PLANE + gx * NX + gy);
    }
    __syncthreads();

    const int npts = g_cnt[bin];
    const int off  = g_off[bin];
    const int lane = tid & 31;
    const int warp = tid >> 5;
    const int cp   = lane & 7;            // channel pair
    const int q    = lane >> 3;           // point slot within warp (0..3)

    for (int idx = warp * 4 + q; idx < npts; idx += 32) {
        const size_t p = (size_t)(off + idx) * 3;
        const float4 r0 = __ldg(&g_pts[p + 0]);
        const float4 r1 = __ldg(&g_pts[p + 1]);
        const float4 r2 = __ldg(&g_pts[p + 2]);
        const float w9[9] = {r0.x, r0.y, r0.z, r0.w, r1.x, r1.y, r1.z, r1.w, r2.x};
        const int n   = __float_as_int(r2.y);
        const int irx = __float_as_int(r2.z);
        const int iry = __float_as_int(r2.w);

        int lxs[3], lys[3];
        #pragma unroll
        for (int a = 0; a < 3; a++) {
            lxs[a] = min(max(irx + 1 - a, 0), NX - 1) - (oX - 1);
            lys[a] = min(max(iry + 1 - a, 0), NX - 1) - (oY - 1);
        }

        float ax = 0.f, ay = 0.f;
        #pragma unroll
        for (int a = 0; a < 3; a++)
            #pragma unroll
            for (int c2 = 0; c2 < 3; c2++) {
                const float w = w9[a * 3 + c2];
                const float2 v = *(const float2*)&s[(size_t)(lxs[a] * TH + lys[c2]) * CST + 2 * cp];
                ax += w * v.x;
                ay += w * v.y;
            }
        // (b, n, c) scratch: 8 lanes write 64B contiguous per point
        *(float2*)&g_outT[((size_t)b * NPTS + n) * CCH + c0 + 2 * cp] = make_float2(ax, ay);
    }
}

// ---------------------------------------------------------------------------
// Final transpose (b, n, c) -> (b, c, n): tiles of 32 n x 64 c.
// ---------------------------------------------------------------------------
__global__ __launch_bounds__(256) void out_transpose_kernel(float* __restrict__ out) {
    __shared__ float s[CCH][33];
    const int blk = blockIdx.x;
    const int b   = blk >> 10;               // NPTS/32 = 1024 tiles per batch
    const int n0  = (blk & 1023) * 32;

    const float* src = g_outT + ((size_t)b * NPTS + n0) * CCH;
    for (int i = threadIdx.x; i < 32 * CCH; i += 256) {
        const int nl = i >> 6;
        const int c  = i & 63;
        s[c][nl] = src[(size_t)nl * CCH + c];   // 256B coalesced reads
    }
    __syncthreads();
    float* dst = out + (size_t)b * CCH * NPTS + n0;
    for (int i = threadIdx.x; i < 32 * CCH; i += 256) {
        const int c  = i >> 5;
        const int nl = i & 31;
        dst[(size_t)c * NPTS + nl] = s[c][nl];  // 128B coalesced writes
    }
}

// ---------------------------------------------------------------------------
extern "C" void kernel_launch(void* const* d_in, const int* in_sizes, int n_in,
                              void* d_out, int out_size) {
    const float* x      = (const float*)d_in[0];
    const float* coords = (const float*)d_in[1];
    if (n_in >= 2 && in_sizes[0] == NB * NPTS * 2) {   // defensive swap
        const float* t = x; x = coords; coords = t;
    }
    float* out = (float*)d_out;

    static bool attr_done = false;
    if (!attr_done) {
        cudaFuncSetAttribute(main_kernel, cudaFuncAttributeMaxDynamicSharedMemorySize,
                             TH * TH * CST * 4);
        attr_done = true;
    }

    zero_kernel<<<4, 256>>>();
    count_kernel<<<NPTS_TOT / 256, 256>>>(coords);
    scan_kernel<<<1, 1024>>>();
    scatter_kernel<<<NPTS_TOT / 256, 256>>>(coords);
    main_kernel<<<NBINS * 4, 256, TH * TH * CST * 4>>>(x);
    out_transpose_kernel<<<NB * (NPTS / 32), 256>>>(out);
}

// round 4
// speedup vs baseline: 3.5002x; 3.5002x over previous
#include <cuda_runtime.h>
#include <cuda_fp16.h>

#define NX    512
#define NPTS  32768
#define CCH   64
#define NB    4
#define PLANE (NX * NX)            // 262144 pixels per plane
#define BVOL  (PLANE * CCH)        // floats per batch

// Scratch: x transposed to NHWC (b, py, px, c) in fp16. 134 MB.
__device__ __half g_xt[(size_t)NB * BVOL];

// ---------------------------------------------------------------------------
// Kernel 1: NCHW fp32 -> NHWC fp16. Tile = 64 pixels x 64 channels.
// Grid: NB * (PLANE/64) = 16384 blocks x 256 threads.
// ---------------------------------------------------------------------------
__global__ __launch_bounds__(256) void transpose_kernel(const float* __restrict__ x)
{
    __shared__ float s[64][66];               // [pixel][channel], even stride

    const int tile = blockIdx.x;
    const int b    = tile >> 12;              // 4096 tiles per batch
    const int p0   = (tile & 4095) * 64;

    const int pl = threadIdx.x & 63;          // pixel within tile
    const int c0 = threadIdx.x >> 6;          // 0..3

    const float* xb = x + (size_t)b * BVOL;
    #pragma unroll
    for (int c = c0; c < 64; c += 4)
        s[pl][c] = xb[(size_t)c * PLANE + p0 + pl];     // 256B coalesced reads

    __syncthreads();

    __half* yb = g_xt + (size_t)b * BVOL + (size_t)p0 * CCH;
    #pragma unroll
    for (int i = threadIdx.x; i < 64 * 32; i += 256) {
        const int p  = i >> 5;                // pixel
        const int cp = i & 31;                // channel pair
        const float2 v = *(const float2*)&s[p][2 * cp]; // conflict-free LDS.64
        ((__half2*)(yb + (size_t)p * CCH))[cp] = __floats2half2_rn(v.x, v.y);
    }   // lanes 0..31 -> 128B coalesced store per pixel
}

// ---------------------------------------------------------------------------
// Kernel 2: gather. Block = 256 threads, 32 consecutive points.
// Warp 0 computes per-point normalized 3x3 weights + NHWC offsets; then each
// warp processes 4 points, lane = channel pair (half2 -> 128B/warp per tap).
// ---------------------------------------------------------------------------
__global__ __launch_bounds__(256) void gather_kernel(
    const float* __restrict__ coords,
    float*       __restrict__ out)
{
    __shared__ float  s_w[32][9];
    __shared__ int    s_off[32][9];       // half-element offset within NHWC batch
    __shared__ float2 s_out[32][33];      // [channel pair][point], padded

    const int p0g = blockIdx.x * 32;
    const int b   = p0g / NPTS;
    const int n0  = p0g % NPTS;
    const int tid = threadIdx.x;

    // ---- Phase 1: weights (identical math to the passing kernels) ----
    if (tid < 32) {
        const int   n    = n0 + tid;
        const float cy   = coords[((size_t)b * NPTS + n) * 2 + 0];
        const float cx   = coords[((size_t)b * NPTS + n) * 2 + 1];
        const float posx = cx * 511.0f;
        const float posy = cy * 511.0f;
        const float rx   = rintf(posx);   // jnp.round = half-to-even
        const float ry   = rintf(posy);

        float wx[3] = {0.f, 0.f, 0.f};
        float wy[3] = {0.f, 0.f, 0.f};
        #pragma unroll
        for (int j = 0; j < 9; j++) {
            const float o  = 1.5f - 0.375f * (float)j;          // off_n[j]
            const float px = fminf(fmaxf(rx - o, 0.f), 512.f);  // clip hi = nx (ref quirk)
            const float py = fminf(fmaxf(ry - o, 0.f), 512.f);
            const float dx = px - posx;
            const float dy = py - posy;
            wx[j / 3] += __expf(-2.f * dx * dx);  // normal const cancels in norm
            wy[j / 3] += __expf(-2.f * dy * dy);
        }

        float w9[9];
        float s = 0.f;
        #pragma unroll
        for (int a = 0; a < 3; a++)
            #pragma unroll
            for (int c2 = 0; c2 < 3; c2++) {
                const float w = wx[a] * wy[c2];
                w9[a * 3 + c2] = w;
                s += w;
            }
        const float inv = 1.0f / s;

        const int irx = (int)rx;
        const int iry = (int)ry;
        int ixs[3], iys[3];
        #pragma unroll
        for (int a = 0; a < 3; a++) {
            ixs[a] = min(max(irx + 1 - a, 0), NX - 1);
            iys[a] = min(max(iry + 1 - a, 0), NX - 1);
        }

        #pragma unroll
        for (int a = 0; a < 3; a++)
            #pragma unroll
            for (int c2 = 0; c2 < 3; c2++) {
                s_w[tid][a * 3 + c2]   = w9[a * 3 + c2] * inv;
                s_off[tid][a * 3 + c2] = (ixs[a] * NX + iys[c2]) * CCH;
            }
    }
    __syncthreads();

    // ---- Phase 2: dense fp16 NHWC gather ----
    const int lane = tid & 31;
    const int warp = tid >> 5;

    const __half* base = g_xt + (size_t)b * BVOL + 2 * lane;   // lane's chan pair

    #pragma unroll
    for (int qq = 0; qq < 4; qq += 2) {
        const int q0 = warp * 4 + qq;
        const int q1 = q0 + 1;
        float2 a0 = make_float2(0.f, 0.f);
        float2 a1 = make_float2(0.f, 0.f);
        #pragma unroll
        for (int k = 0; k < 9; k++) {
            const float2 v0 = __half22float2(*(const __half2*)(base + s_off[q0][k]));
            const float2 v1 = __half22float2(*(const __half2*)(base + s_off[q1][k]));
            const float  w0 = s_w[q0][k];
            const float  w1 = s_w[q1][k];
            a0.x += w0 * v0.x;  a0.y += w0 * v0.y;
            a1.x += w1 * v1.x;  a1.y += w1 * v1.y;
        }
        s_out[lane][q0] = a0;
        s_out[lane][q1] = a1;
    }
    __syncthreads();

    // ---- Phase 3: coalesced (c, n) writes: 128B per channel row ----
    float* ob = out + (size_t)b * CCH * NPTS + n0;
    #pragma unroll
    for (int i = tid; i < CCH * 32; i += 256) {
        const int j = i & 31;         // point within block
        const int c = i >> 5;         // channel
        const float2 v = s_out[c >> 1][j];
        ob[(size_t)c * NPTS + j] = (c & 1) ? v.y : v.x;
    }
}

extern "C" void kernel_launch(void* const* d_in, const int* in_sizes, int n_in,
                              void* d_out, int out_size) {
    const float* x      = (const float*)d_in[0];
    const float* coords = (const float*)d_in[1];
    if (n_in >= 2 && in_sizes[0] == NB * NPTS * 2) {  // defensive swap
        const float* t = x; x = coords; coords = t;
    }
    float* out = (float*)d_out;

    transpose_kernel<<<NB * (PLANE / 64), 256>>>(x);
    gather_kernel<<<(NB * NPTS) / 32, 256>>>(coords, out);
}